// round 1
// baseline (speedup 1.0000x reference)
#include <cuda_runtime.h>
#include <math.h>

static constexpr int BATCH = 64;
static constexpr int H  = 256;
static constexpr int W  = 256;
static constexpr int HW = H * W;          // 65536
static constexpr int HW4 = HW / 4;        // 16384 float4 groups per channel
static constexpr int NK = 68;

// Per-batch similarity transform: 9 floats sR (row-major [d][c]) + 3 floats t.
__device__ float g_params[BATCH * 12];

// ---------------------------------------------------------------------------
// Kernel 1: per-batch Umeyama estimation (64 blocks x 128 threads)
// ---------------------------------------------------------------------------
__global__ void estimate_kernel(const float* __restrict__ Off,
                                const float* __restrict__ Pos,
                                const float* __restrict__ Mp,
                                const int*   __restrict__ uv)
{
    const int b   = blockIdx.x;
    const int tid = threadIdx.x;

    __shared__ float red[10][128];
    __shared__ float mus[3], mud[3];

    float s0 = 0.f, s1 = 0.f, s2 = 0.f;
    float d0 = 0.f, d1 = 0.f, d2 = 0.f;

    if (tid < NK) {
        const int h = uv[2 * tid + 0];
        const int w = uv[2 * tid + 1];
        const int base = b * 3 * HW + h * W + w;
        const int mb   = h * W + w;
        // offsetmap = (Offset*4 + mean) * REVERT, REVERT = [1,-1,1]
        s0 =  fmaf(Off[base         ], 4.0f, Mp[mb         ]);
        s1 = -fmaf(Off[base +    HW ], 4.0f, Mp[mb +    HW ]);
        s2 =  fmaf(Off[base + 2*HW  ], 4.0f, Mp[mb + 2*HW  ]);
        d0 = Pos[base];
        d1 = Pos[base + HW];
        d2 = Pos[base + 2 * HW];
    }

    // --- reduce the 6 coordinate sums to get the means ---
    red[0][tid] = s0; red[1][tid] = s1; red[2][tid] = s2;
    red[3][tid] = d0; red[4][tid] = d1; red[5][tid] = d2;
    __syncthreads();
    for (int st = 64; st > 0; st >>= 1) {
        if (tid < st) {
            #pragma unroll
            for (int k = 0; k < 6; k++) red[k][tid] += red[k][tid + st];
        }
        __syncthreads();
    }
    if (tid == 0) {
        mus[0] = red[0][0] / NK; mus[1] = red[1][0] / NK; mus[2] = red[2][0] / NK;
        mud[0] = red[3][0] / NK; mud[1] = red[4][0] / NK; mud[2] = red[5][0] / NK;
    }
    __syncthreads();

    // --- per-point contributions to A = dd^T sd / n and var_s ---
    float a[9] = {0,0,0,0,0,0,0,0,0};
    float var  = 0.f;
    if (tid < NK) {
        const float c0 = s0 - mus[0], c1 = s1 - mus[1], c2 = s2 - mus[2];
        const float e0 = d0 - mud[0], e1 = d1 - mud[1], e2 = d2 - mud[2];
        a[0] = e0 * c0; a[1] = e0 * c1; a[2] = e0 * c2;
        a[3] = e1 * c0; a[4] = e1 * c1; a[5] = e1 * c2;
        a[6] = e2 * c0; a[7] = e2 * c1; a[8] = e2 * c2;
        var  = c0 * c0 + c1 * c1 + c2 * c2;
    }
    #pragma unroll
    for (int k = 0; k < 9; k++) red[k][tid] = a[k];
    red[9][tid] = var;
    __syncthreads();
    for (int st = 64; st > 0; st >>= 1) {
        if (tid < st) {
            #pragma unroll
            for (int k = 0; k < 10; k++) red[k][tid] += red[k][tid + st];
        }
        __syncthreads();
    }

    // --- thread 0: 3x3 SVD (Jacobi on A^T A, double precision) + transform ---
    if (tid == 0) {
        double A[3][3];
        #pragma unroll
        for (int i = 0; i < 3; i++)
            #pragma unroll
            for (int j = 0; j < 3; j++)
                A[i][j] = (double)red[i * 3 + j][0] / NK;
        const double var_s = (double)red[9][0] / NK;

        const double detA =
              A[0][0] * (A[1][1] * A[2][2] - A[1][2] * A[2][1])
            - A[0][1] * (A[1][0] * A[2][2] - A[1][2] * A[2][0])
            + A[0][2] * (A[1][0] * A[2][1] - A[1][1] * A[2][0]);

        // Bm = A^T A (symmetric PSD)
        double Bm[3][3], Vm[3][3] = {{1,0,0},{0,1,0},{0,0,1}};
        #pragma unroll
        for (int i = 0; i < 3; i++)
            #pragma unroll
            for (int j = 0; j < 3; j++) {
                double acc = 0.0;
                #pragma unroll
                for (int k = 0; k < 3; k++) acc += A[k][i] * A[k][j];
                Bm[i][j] = acc;
            }

        // Cyclic Jacobi — 20 sweeps is far past convergence for 3x3
        const int PP[3] = {0, 0, 1}, QQ[3] = {1, 2, 2};
        for (int sweep = 0; sweep < 20; sweep++) {
            for (int r = 0; r < 3; r++) {
                const int p = PP[r], q = QQ[r];
                const double apq = Bm[p][q];
                if (fabs(apq) < 1e-300) continue;
                const double theta = (Bm[q][q] - Bm[p][p]) / (2.0 * apq);
                const double tt = ((theta >= 0.0) ? 1.0 : -1.0) /
                                  (fabs(theta) + sqrt(theta * theta + 1.0));
                const double c = 1.0 / sqrt(tt * tt + 1.0);
                const double s = tt * c;
                for (int k = 0; k < 3; k++) {
                    const double bkp = Bm[k][p], bkq = Bm[k][q];
                    Bm[k][p] = c * bkp - s * bkq;
                    Bm[k][q] = s * bkp + c * bkq;
                }
                for (int k = 0; k < 3; k++) {
                    const double bpk = Bm[p][k], bqk = Bm[q][k];
                    Bm[p][k] = c * bpk - s * bqk;
                    Bm[q][k] = s * bpk + c * bqk;
                }
                for (int k = 0; k < 3; k++) {
                    const double vkp = Vm[k][p], vkq = Vm[k][q];
                    Vm[k][p] = c * vkp - s * vkq;
                    Vm[k][q] = s * vkp + c * vkq;
                }
            }
        }

        double wv[3] = {Bm[0][0], Bm[1][1], Bm[2][2]};
        int id[3] = {0, 1, 2};
        if (wv[id[0]] < wv[id[1]]) { int t = id[0]; id[0] = id[1]; id[1] = t; }
        if (wv[id[1]] < wv[id[2]]) { int t = id[1]; id[1] = id[2]; id[2] = t; }
        if (wv[id[0]] < wv[id[1]]) { int t = id[0]; id[0] = id[1]; id[1] = t; }

        double U[3][3], Vc[3][3], sv[3];
        for (int i = 0; i < 3; i++) {
            const int j = id[i];
            const double v0 = Vm[0][j], v1 = Vm[1][j], v2 = Vm[2][j];
            const double u0 = A[0][0] * v0 + A[0][1] * v1 + A[0][2] * v2;
            const double u1 = A[1][0] * v0 + A[1][1] * v1 + A[1][2] * v2;
            const double u2 = A[2][0] * v0 + A[2][1] * v1 + A[2][2] * v2;
            const double nu = sqrt(u0 * u0 + u1 * u1 + u2 * u2);  // == sigma_i
            sv[i] = nu;
            const double inv = (nu > 1e-300) ? 1.0 / nu : 0.0;
            U[0][i] = u0 * inv; U[1][i] = u1 * inv; U[2][i] = u2 * inv;
            Vc[0][i] = v0; Vc[1][i] = v1; Vc[2][i] = v2;
        }

        const double d3 = (detA < 0.0) ? -1.0 : 1.0;
        const double dd[3] = {1.0, 1.0, d3};
        const double scale = (sv[0] + sv[1] + d3 * sv[2]) / var_s;

        float* outp = g_params + b * 12;
        for (int r = 0; r < 3; r++) {
            double row[3];
            for (int c = 0; c < 3; c++) {
                double acc = 0.0;
                for (int i = 0; i < 3; i++) acc += dd[i] * U[r][i] * Vc[c][i];
                row[c] = scale * acc;
                outp[r * 3 + c] = (float)row[c];
            }
            const double tr = (double)mud[r]
                - (row[0] * (double)mus[0] + row[1] * (double)mus[1] + row[2] * (double)mus[2]);
            outp[9 + r] = (float)tr;
        }
    }
}

// ---------------------------------------------------------------------------
// Kernel 2: apply transform to the full 64x3x256x256 map (HBM-bound, float4)
// ---------------------------------------------------------------------------
__global__ void __launch_bounds__(256)
apply_kernel(const float4* __restrict__ Off,
             const float4* __restrict__ Mp,
             float4*       __restrict__ Out)
{
    const int idx = blockIdx.x * blockDim.x + threadIdx.x;  // 64*16384 threads
    const int b = idx >> 14;            // 16384 float4 groups per batch image
    const int g = idx & 16383;

    const float* p = g_params + b * 12; // uniform per block -> broadcast loads
    const float p00 = p[0], p01 = p[1], p02 = p[2];
    const float p10 = p[3], p11 = p[4], p12 = p[5];
    const float p20 = p[6], p21 = p[7], p22 = p[8];
    const float t0  = p[9], t1  = p[10], t2 = p[11];

    const int base = b * 3 * HW4 + g;
    const float4 o0 = Off[base];
    const float4 o1 = Off[base + HW4];
    const float4 o2 = Off[base + 2 * HW4];
    const float4 m0 = Mp[g];
    const float4 m1 = Mp[g + HW4];
    const float4 m2 = Mp[g + 2 * HW4];

    float4 r0, r1, r2;

#define APPLY_LANE(j)                                                        \
    {                                                                        \
        const float x =  fmaf(o0.j, 4.0f, m0.j);                             \
        const float y = -fmaf(o1.j, 4.0f, m1.j);                             \
        const float z =  fmaf(o2.j, 4.0f, m2.j);                             \
        r0.j = fmaf(p00, x, fmaf(p01, y, fmaf(p02, z, t0)));                 \
        r1.j = fmaf(p10, x, fmaf(p11, y, fmaf(p12, z, t1)));                 \
        r2.j = fmaf(p20, x, fmaf(p21, y, fmaf(p22, z, t2)));                 \
    }

    APPLY_LANE(x)
    APPLY_LANE(y)
    APPLY_LANE(z)
    APPLY_LANE(w)
#undef APPLY_LANE

    Out[base]           = r0;
    Out[base + HW4]     = r1;
    Out[base + 2 * HW4] = r2;
}

// ---------------------------------------------------------------------------
extern "C" void kernel_launch(void* const* d_in, const int* in_sizes, int n_in,
                              void* d_out, int out_size)
{
    const float* Off = (const float*)d_in[0];   // [64,3,256,256]
    const float* Pos = (const float*)d_in[1];   // [64,3,256,256]
    const float* Mp  = (const float*)d_in[2];   // [3,256,256]
    const int*   uv  = (const int*)  d_in[3];   // [68,2]
    float*       Out = (float*)d_out;           // [64,3,256,256]

    estimate_kernel<<<BATCH, 128>>>(Off, Pos, Mp, uv);

    const int total4 = BATCH * HW4;             // 1,048,576 threads
    apply_kernel<<<total4 / 256, 256>>>((const float4*)Off,
                                        (const float4*)Mp,
                                        (float4*)Out);
}

// round 2
// speedup vs baseline: 2.0528x; 2.0528x over previous
#include <cuda_runtime.h>
#include <math.h>

static constexpr int BATCH = 64;
static constexpr int H  = 256;
static constexpr int W  = 256;
static constexpr int HW = H * W;          // 65536
static constexpr int HW4 = HW / 4;        // 16384 float4 groups per channel
static constexpr int NK = 68;

// Per-batch similarity transform: 9 floats sR (row-major [d][c]) + 3 floats t.
__device__ float g_params[BATCH * 12];

// ---------------------------------------------------------------------------
// Kernel 1: per-batch Umeyama estimation (64 blocks x 128 threads)
// Serial 3x3 SVD now in fp32 (FFMA lat 4) with 6 Jacobi sweeps instead of the
// fp64 / 20-sweep version that cost ~39us.
// ---------------------------------------------------------------------------
__global__ void estimate_kernel(const float* __restrict__ Off,
                                const float* __restrict__ Pos,
                                const float* __restrict__ Mp,
                                const int*   __restrict__ uv)
{
    const int b   = blockIdx.x;
    const int tid = threadIdx.x;

    __shared__ float red[10][128];
    __shared__ float mus[3], mud[3];

    float s0 = 0.f, s1 = 0.f, s2 = 0.f;
    float d0 = 0.f, d1 = 0.f, d2 = 0.f;

    if (tid < NK) {
        const int h = uv[2 * tid + 0];
        const int w = uv[2 * tid + 1];
        const int base = b * 3 * HW + h * W + w;
        const int mb   = h * W + w;
        // offsetmap = (Offset*4 + mean) * REVERT, REVERT = [1,-1,1]
        s0 =  fmaf(Off[base         ], 4.0f, Mp[mb         ]);
        s1 = -fmaf(Off[base +    HW ], 4.0f, Mp[mb +    HW ]);
        s2 =  fmaf(Off[base + 2*HW  ], 4.0f, Mp[mb + 2*HW  ]);
        d0 = Pos[base];
        d1 = Pos[base + HW];
        d2 = Pos[base + 2 * HW];
    }

    // --- reduce the 6 coordinate sums to get the means ---
    red[0][tid] = s0; red[1][tid] = s1; red[2][tid] = s2;
    red[3][tid] = d0; red[4][tid] = d1; red[5][tid] = d2;
    __syncthreads();
    for (int st = 64; st > 0; st >>= 1) {
        if (tid < st) {
            #pragma unroll
            for (int k = 0; k < 6; k++) red[k][tid] += red[k][tid + st];
        }
        __syncthreads();
    }
    if (tid == 0) {
        mus[0] = red[0][0] / NK; mus[1] = red[1][0] / NK; mus[2] = red[2][0] / NK;
        mud[0] = red[3][0] / NK; mud[1] = red[4][0] / NK; mud[2] = red[5][0] / NK;
    }
    __syncthreads();

    // --- per-point contributions to A = dd^T sd / n and var_s ---
    float a[9] = {0,0,0,0,0,0,0,0,0};
    float var  = 0.f;
    if (tid < NK) {
        const float c0 = s0 - mus[0], c1 = s1 - mus[1], c2 = s2 - mus[2];
        const float e0 = d0 - mud[0], e1 = d1 - mud[1], e2 = d2 - mud[2];
        a[0] = e0 * c0; a[1] = e0 * c1; a[2] = e0 * c2;
        a[3] = e1 * c0; a[4] = e1 * c1; a[5] = e1 * c2;
        a[6] = e2 * c0; a[7] = e2 * c1; a[8] = e2 * c2;
        var  = c0 * c0 + c1 * c1 + c2 * c2;
    }
    #pragma unroll
    for (int k = 0; k < 9; k++) red[k][tid] = a[k];
    red[9][tid] = var;
    __syncthreads();
    for (int st = 64; st > 0; st >>= 1) {
        if (tid < st) {
            #pragma unroll
            for (int k = 0; k < 10; k++) red[k][tid] += red[k][tid + st];
        }
        __syncthreads();
    }

    // --- thread 0: 3x3 SVD (fp32 cyclic Jacobi on A^T A) + transform ---
    if (tid == 0) {
        float A[3][3];
        #pragma unroll
        for (int i = 0; i < 3; i++)
            #pragma unroll
            for (int j = 0; j < 3; j++)
                A[i][j] = red[i * 3 + j][0] * (1.0f / NK);
        const float var_s = red[9][0] * (1.0f / NK);

        const float detA =
              A[0][0] * (A[1][1] * A[2][2] - A[1][2] * A[2][1])
            - A[0][1] * (A[1][0] * A[2][2] - A[1][2] * A[2][0])
            + A[0][2] * (A[1][0] * A[2][1] - A[1][1] * A[2][0]);

        // Bm = A^T A (symmetric PSD)
        float Bm[3][3], Vm[3][3] = {{1,0,0},{0,1,0},{0,0,1}};
        #pragma unroll
        for (int i = 0; i < 3; i++)
            #pragma unroll
            for (int j = 0; j < 3; j++) {
                float acc = 0.0f;
                #pragma unroll
                for (int k = 0; k < 3; k++) acc += A[k][i] * A[k][j];
                Bm[i][j] = acc;
            }

        // Cyclic Jacobi, fp32. Off-diagonals decay cubically; 6 sweeps is
        // well past fp32 machine precision for 3x3.
        const int PP[3] = {0, 0, 1}, QQ[3] = {1, 2, 2};
        #pragma unroll 1
        for (int sweep = 0; sweep < 6; sweep++) {
            #pragma unroll
            for (int r = 0; r < 3; r++) {
                const int p = PP[r], q = QQ[r];
                const float apq = Bm[p][q];
                if (fabsf(apq) < 1e-30f) continue;
                const float theta = (Bm[q][q] - Bm[p][p]) / (2.0f * apq);
                const float tt = ((theta >= 0.0f) ? 1.0f : -1.0f) /
                                 (fabsf(theta) + sqrtf(theta * theta + 1.0f));
                const float c = rsqrtf(tt * tt + 1.0f);
                const float s = tt * c;
                #pragma unroll
                for (int k = 0; k < 3; k++) {
                    const float bkp = Bm[k][p], bkq = Bm[k][q];
                    Bm[k][p] = c * bkp - s * bkq;
                    Bm[k][q] = s * bkp + c * bkq;
                }
                #pragma unroll
                for (int k = 0; k < 3; k++) {
                    const float bpk = Bm[p][k], bqk = Bm[q][k];
                    Bm[p][k] = c * bpk - s * bqk;
                    Bm[q][k] = s * bpk + c * bqk;
                }
                #pragma unroll
                for (int k = 0; k < 3; k++) {
                    const float vkp = Vm[k][p], vkq = Vm[k][q];
                    Vm[k][p] = c * vkp - s * vkq;
                    Vm[k][q] = s * vkp + c * vkq;
                }
            }
        }

        float wv[3] = {Bm[0][0], Bm[1][1], Bm[2][2]};
        int id[3] = {0, 1, 2};
        if (wv[id[0]] < wv[id[1]]) { int t = id[0]; id[0] = id[1]; id[1] = t; }
        if (wv[id[1]] < wv[id[2]]) { int t = id[1]; id[1] = id[2]; id[2] = t; }
        if (wv[id[0]] < wv[id[1]]) { int t = id[0]; id[0] = id[1]; id[1] = t; }

        float U[3][3], Vc[3][3], sv[3];
        #pragma unroll
        for (int i = 0; i < 3; i++) {
            const int j = id[i];
            const float v0 = Vm[0][j], v1 = Vm[1][j], v2 = Vm[2][j];
            const float u0 = A[0][0] * v0 + A[0][1] * v1 + A[0][2] * v2;
            const float u1 = A[1][0] * v0 + A[1][1] * v1 + A[1][2] * v2;
            const float u2 = A[2][0] * v0 + A[2][1] * v1 + A[2][2] * v2;
            const float nu = sqrtf(u0 * u0 + u1 * u1 + u2 * u2);  // == sigma_i
            sv[i] = nu;
            const float inv = (nu > 1e-30f) ? 1.0f / nu : 0.0f;
            U[0][i] = u0 * inv; U[1][i] = u1 * inv; U[2][i] = u2 * inv;
            Vc[0][i] = v0; Vc[1][i] = v1; Vc[2][i] = v2;
        }

        const float d3 = (detA < 0.0f) ? -1.0f : 1.0f;
        const float dd[3] = {1.0f, 1.0f, d3};
        const float scale = (sv[0] + sv[1] + d3 * sv[2]) / var_s;

        float* outp = g_params + b * 12;
        #pragma unroll
        for (int r = 0; r < 3; r++) {
            float row[3];
            #pragma unroll
            for (int c = 0; c < 3; c++) {
                float acc = 0.0f;
                #pragma unroll
                for (int i = 0; i < 3; i++) acc += dd[i] * U[r][i] * Vc[c][i];
                row[c] = scale * acc;
                outp[r * 3 + c] = row[c];
            }
            outp[9 + r] = mud[r]
                - (row[0] * mus[0] + row[1] * mus[1] + row[2] * mus[2]);
        }
    }
}

// ---------------------------------------------------------------------------
// Kernel 2: apply transform to the full 64x3x256x256 map (HBM-bound, float4)
// ---------------------------------------------------------------------------
__global__ void __launch_bounds__(256)
apply_kernel(const float4* __restrict__ Off,
             const float4* __restrict__ Mp,
             float4*       __restrict__ Out)
{
    const int idx = blockIdx.x * blockDim.x + threadIdx.x;  // 64*16384 threads
    const int b = idx >> 14;            // 16384 float4 groups per batch image
    const int g = idx & 16383;

    const float* p = g_params + b * 12; // uniform per block -> broadcast loads
    const float p00 = p[0], p01 = p[1], p02 = p[2];
    const float p10 = p[3], p11 = p[4], p12 = p[5];
    const float p20 = p[6], p21 = p[7], p22 = p[8];
    const float t0  = p[9], t1  = p[10], t2 = p[11];

    const int base = b * 3 * HW4 + g;
    // Offset is read once -> streaming loads; mean_posmap is reused 64x -> keep cached.
    const float4 o0 = __ldcs(&Off[base]);
    const float4 o1 = __ldcs(&Off[base + HW4]);
    const float4 o2 = __ldcs(&Off[base + 2 * HW4]);
    const float4 m0 = __ldg(&Mp[g]);
    const float4 m1 = __ldg(&Mp[g + HW4]);
    const float4 m2 = __ldg(&Mp[g + 2 * HW4]);

    float4 r0, r1, r2;

#define APPLY_LANE(j)                                                        \
    {                                                                        \
        const float x =  fmaf(o0.j, 4.0f, m0.j);                             \
        const float y = -fmaf(o1.j, 4.0f, m1.j);                             \
        const float z =  fmaf(o2.j, 4.0f, m2.j);                             \
        r0.j = fmaf(p00, x, fmaf(p01, y, fmaf(p02, z, t0)));                 \
        r1.j = fmaf(p10, x, fmaf(p11, y, fmaf(p12, z, t1)));                 \
        r2.j = fmaf(p20, x, fmaf(p21, y, fmaf(p22, z, t2)));                 \
    }

    APPLY_LANE(x)
    APPLY_LANE(y)
    APPLY_LANE(z)
    APPLY_LANE(w)
#undef APPLY_LANE

    __stcs(&Out[base],           r0);
    __stcs(&Out[base + HW4],     r1);
    __stcs(&Out[base + 2 * HW4], r2);
}

// ---------------------------------------------------------------------------
extern "C" void kernel_launch(void* const* d_in, const int* in_sizes, int n_in,
                              void* d_out, int out_size)
{
    const float* Off = (const float*)d_in[0];   // [64,3,256,256]
    const float* Pos = (const float*)d_in[1];   // [64,3,256,256]
    const float* Mp  = (const float*)d_in[2];   // [3,256,256]
    const int*   uv  = (const int*)  d_in[3];   // [68,2]
    float*       Out = (float*)d_out;           // [64,3,256,256]

    estimate_kernel<<<BATCH, 128>>>(Off, Pos, Mp, uv);

    const int total4 = BATCH * HW4;             // 1,048,576 threads
    apply_kernel<<<total4 / 256, 256>>>((const float4*)Off,
                                        (const float4*)Mp,
                                        (float4*)Out);
}